// round 15
// baseline (speedup 1.0000x reference)
#include <cuda_runtime.h>
#include <cuda_fp16.h>

#define NN 100000
#define NE 3200000
#define HID 16
#define OUTC 64
#define INC 128
#define CAP 128   // per-node capacity (deg ~ Poisson(32); 12-sigma safe, fixed input graph)

// packed fp32x2 FMA (sm_103a; ptxas never emits FFMA2 from C++)
#define FMA_F32X2(d, a, b, c) \
    asm("fma.rn.f32x2 %0, %1, %2, %3;" : "=l"(d) : "l"(a), "l"(b), "l"(c))
#define PACK_F32X2(out, lo, hi) \
    asm("mov.b64 %0, {%1, %2};" : "=l"(out) : "f"(lo), "f"(hi))
#define UNPACK_F32X2(lo, hi, in) \
    asm("mov.b64 {%0, %1}, %2;" : "=f"(lo), "=f"(hi) : "l"(in))

// ---- scratch (device globals; .bss zero-initialized at module load) ----
__device__ int    g_cnt[NN];               // invariant: zero at entry (re-zeroed in k_gather2)
__device__ float  g_dinv[NN];
__device__ int    g_rowidx[NN * CAP + 4];  // +4: prefetch over-read pad
__device__ float  g_xW1r[NN * HID];        // raw x@W1 (fp32)
__device__ __align__(16) __half g_xW1h[NN * HID];  // (x@W1)*dinv, fp16 rows (32 B)
__device__ float  g_id1[NN * HID];         // x@T1 + t1b (fp32)
__device__ __align__(16) __half g_hsh[NN * HID];   // (relu+id1)*dn, fp16 rows (32 B)
__device__ float  g_agg[NN * HID];         // layer-2 aggregate (fp32)

// ---- second stream + events (created pre-main; no device memory) ----
static cudaStream_t g_s2;
static cudaEvent_t  g_evFork, g_evS2;
namespace {
struct S2Init {
    S2Init() {
        cudaStreamCreateWithFlags(&g_s2, cudaStreamNonBlocking);
        cudaEventCreateWithFlags(&g_evFork, cudaEventDisableTiming);
        cudaEventCreateWithFlags(&g_evS2, cudaEventDisableTiming);
    }
};
static S2Init s2init;
}

// ---- single-pass bucket fill ----
__global__ void k_fill2(const int* __restrict__ ei) {
    int t = blockIdx.x * blockDim.x + threadIdx.x;
    if (t < NE / 4) {
        int4 r4 = ((const int4*)ei)[t];
        int4 c4 = ((const int4*)(ei + NE))[t];
        g_rowidx[c4.x * CAP + atomicAdd(&g_cnt[c4.x], 1)] = r4.x;
        g_rowidx[c4.y * CAP + atomicAdd(&g_cnt[c4.y], 1)] = r4.y;
        g_rowidx[c4.z * CAP + atomicAdd(&g_cnt[c4.z], 1)] = r4.z;
        g_rowidx[c4.w * CAP + atomicAdd(&g_cnt[c4.w], 1)] = r4.w;
    }
}

// ---- combined GEMM1 (s2): 2 rows/thread, FFMA2. xW1r = x@W1 ; id1 = x@T1+t1b ----
__global__ void __launch_bounds__(128) k_gemm1(const float* __restrict__ x,
                        const float* __restrict__ W1,
                        const float* __restrict__ T1,
                        const float* __restrict__ t1b) {
    __shared__ __align__(16) float ws[INC * 32];   // [k][j]: j<16 W1, j>=16 T1
    for (int i = threadIdx.x; i < INC * HID; i += blockDim.x) {
        int k = i / HID, j = i % HID;
        ws[k * 32 + j]      = W1[i];
        ws[k * 32 + 16 + j] = T1[i];
    }
    __syncthreads();

    int r0 = blockIdx.x * 256 + threadIdx.x;   // rows r0 and r0+128
    int r1 = r0 + 128;
    bool has0 = r0 < NN, has1 = r1 < NN;
    if (!has0) return;

    unsigned long long accA[16], accB[16];
#pragma unroll
    for (int j = 0; j < 16; j++) { accA[j] = 0ULL; accB[j] = 0ULL; }

    const float4* xrA = (const float4*)(x + (size_t)r0 * INC);
    const float4* xrB = (const float4*)(x + (size_t)r1 * INC);
#pragma unroll 4
    for (int kk = 0; kk < INC / 4; kk++) {
        float4 xa = xrA[kk];
        float4 xb = has1 ? xrB[kk] : make_float4(0.f, 0.f, 0.f, 0.f);
        float xsA[4] = {xa.x, xa.y, xa.z, xa.w};
        float xsB[4] = {xb.x, xb.y, xb.z, xb.w};
#pragma unroll
        for (int s = 0; s < 4; s++) {
            unsigned long long xdA, xdB;
            PACK_F32X2(xdA, xsA[s], xsA[s]);
            PACK_F32X2(xdB, xsB[s], xsB[s]);
            const ulonglong2* wrow = (const ulonglong2*)(ws + (kk * 4 + s) * 32);
#pragma unroll
            for (int q = 0; q < 8; q++) {
                ulonglong2 wl = wrow[q];     // LDS.128 broadcast: floats 4q..4q+3
                FMA_F32X2(accA[2 * q],     xdA, wl.x, accA[2 * q]);
                FMA_F32X2(accA[2 * q + 1], xdA, wl.y, accA[2 * q + 1]);
                FMA_F32X2(accB[2 * q],     xdB, wl.x, accB[2 * q]);
                FMA_F32X2(accB[2 * q + 1], xdB, wl.y, accB[2 * q + 1]);
            }
        }
    }

    float a[32], b[32];
#pragma unroll
    for (int j = 0; j < 16; j++) {
        UNPACK_F32X2(a[2 * j], a[2 * j + 1], accA[j]);
        UNPACK_F32X2(b[2 * j], b[2 * j + 1], accB[j]);
    }
    {
        float4* o1 = (float4*)(g_xW1r + r0 * HID);
        float4* o2 = (float4*)(g_id1 + r0 * HID);
#pragma unroll
        for (int q = 0; q < 4; q++) {
            o1[q] = make_float4(a[q * 4 + 0], a[q * 4 + 1], a[q * 4 + 2], a[q * 4 + 3]);
            o2[q] = make_float4(a[16 + q * 4 + 0] + t1b[q * 4 + 0],
                                a[16 + q * 4 + 1] + t1b[q * 4 + 1],
                                a[16 + q * 4 + 2] + t1b[q * 4 + 2],
                                a[16 + q * 4 + 3] + t1b[q * 4 + 3]);
        }
    }
    if (has1) {
        float4* o1 = (float4*)(g_xW1r + r1 * HID);
        float4* o2 = (float4*)(g_id1 + r1 * HID);
#pragma unroll
        for (int q = 0; q < 4; q++) {
            o1[q] = make_float4(b[q * 4 + 0], b[q * 4 + 1], b[q * 4 + 2], b[q * 4 + 3]);
            o2[q] = make_float4(b[16 + q * 4 + 0] + t1b[q * 4 + 0],
                                b[16 + q * 4 + 1] + t1b[q * 4 + 1],
                                b[16 + q * 4 + 2] + t1b[q * 4 + 2],
                                b[16 + q * 4 + 3] + t1b[q * 4 + 3]);
        }
    }
}

// ---- dinv + scale + fp16 pack: xW1h = half(xW1r * dinv) ----
__global__ void k_dinv() {
    int gid = blockIdx.x * blockDim.x + threadIdx.x;   // node*4+q
    int node = gid >> 2;
    if (node >= NN) return;
    float dn = rsqrtf((float)g_cnt[node] + 1.0f);
    if ((gid & 3) == 0) g_dinv[node] = dn;
    float4 v = ((const float4*)g_xW1r)[gid];
    __half2 h0 = __floats2half2_rn(v.x * dn, v.y * dn);
    __half2 h1 = __floats2half2_rn(v.z * dn, v.w * dn);
    uint2 u;
    u.x = *(unsigned int*)&h0;
    u.y = *(unsigned int*)&h1;
    ((uint2*)g_xW1h)[gid] = u;
}

// ---- gather core: fp16 rows (32 B); INDEX PREFETCH breaks the idx->feature chain ----
__device__ __forceinline__ float4 gather_node_h(const __half* __restrict__ srcH,
                                                int node, int q, int deg) {
    const uint2* src2 = (const uint2*)srcH;
    const int4* idx4 = (const int4*)(g_rowidx + node * CAP);
    float4 acc = make_float4(0.f, 0.f, 0.f, 0.f);
    int nIter = deg >> 2;
    if (nIter > 0) {
        int4 r = __ldg(&idx4[0]);
        for (int it = 0; it < nIter; it++) {
            int4 rn = __ldg(&idx4[it + 1]);   // prefetch next (pad makes over-read safe)
            uint2 ua = __ldg(&src2[r.x * 4 + q]);
            uint2 ub = __ldg(&src2[r.y * 4 + q]);
            uint2 uc = __ldg(&src2[r.z * 4 + q]);
            uint2 ud = __ldg(&src2[r.w * 4 + q]);
            float2 a0 = __half22float2(*(__half2*)&ua.x), a1 = __half22float2(*(__half2*)&ua.y);
            float2 b0 = __half22float2(*(__half2*)&ub.x), b1 = __half22float2(*(__half2*)&ub.y);
            float2 c0 = __half22float2(*(__half2*)&uc.x), c1 = __half22float2(*(__half2*)&uc.y);
            float2 d0 = __half22float2(*(__half2*)&ud.x), d1 = __half22float2(*(__half2*)&ud.y);
            acc.x += (a0.x + b0.x) + (c0.x + d0.x);
            acc.y += (a0.y + b0.y) + (c0.y + d0.y);
            acc.z += (a1.x + b1.x) + (c1.x + d1.x);
            acc.w += (a1.y + b1.y) + (c1.y + d1.y);
            r = rn;
        }
    }
    for (int i = nIter << 2; i < deg; i++) {
        int r0 = g_rowidx[node * CAP + i];
        uint2 ua = __ldg(&src2[r0 * 4 + q]);
        float2 a0 = __half22float2(*(__half2*)&ua.x), a1 = __half22float2(*(__half2*)&ua.y);
        acc.x += a0.x; acc.y += a0.y; acc.z += a1.x; acc.w += a1.y;
    }
    uint2 us = __ldg(&src2[node * 4 + q]);   // self loop
    float2 s0 = __half22float2(*(__half2*)&us.x), s1 = __half22float2(*(__half2*)&us.y);
    acc.x += s0.x; acc.y += s0.y; acc.z += s1.x; acc.w += s1.y;
    return acc;
}

// ---- Gather pass 0: hs = half((relu(dn*acc + b1) + id1) * dn) ----
__global__ void k_gather_h(const float* __restrict__ b1) {
    int gid = blockIdx.x * blockDim.x + threadIdx.x;
    int node = gid >> 2;
    int q = gid & 3;
    if (node >= NN) return;

    int deg = g_cnt[node];
    float4 acc = gather_node_h(g_xW1h, node, q, deg);
    float dn = g_dinv[node];
    float4 bb = ((const float4*)b1)[q];
    float4 id = ((const float4*)g_id1)[gid];
    float hx = (fmaxf(dn * acc.x + bb.x, 0.f) + id.x) * dn;
    float hy = (fmaxf(dn * acc.y + bb.y, 0.f) + id.y) * dn;
    float hz = (fmaxf(dn * acc.z + bb.z, 0.f) + id.z) * dn;
    float hw = (fmaxf(dn * acc.w + bb.w, 0.f) + id.w) * dn;
    __half2 h0 = __floats2half2_rn(hx, hy);
    __half2 h1 = __floats2half2_rn(hz, hw);
    uint2 u;
    u.x = *(unsigned int*)&h0;
    u.y = *(unsigned int*)&h1;
    ((uint2*)g_hsh)[gid] = u;
}

// ---- Gather pass 1 (no block barrier): agg = dn * acc(hs); restores cnt=0 ----
__global__ void k_gather2() {
    int gid = blockIdx.x * blockDim.x + threadIdx.x;
    int node = gid >> 2;
    int q = gid & 3;
    if (node >= NN) return;

    int deg = g_cnt[node];               // all 4 q-lanes read (same warp, same instr)
    float4 acc = gather_node_h(g_hsh, node, q, deg);
    float dn = g_dinv[node];
    ((float4*)g_agg)[gid] =
        make_float4(dn * acc.x, dn * acc.y, dn * acc.z, dn * acc.w);
    if (q == 0) g_cnt[node] = 0;         // restore invariant (after the warp's reads)
}

// ---- Output GEMM: out = relu(agg@W2 + b2) + (hs@T2)*rcp(dinv) + t2b ----
__global__ void k_out(const float* __restrict__ W2,
                      const float* __restrict__ b2,
                      const float* __restrict__ T2,
                      const float* __restrict__ t2b,
                      float* __restrict__ out) {
    int tid = threadIdx.x;
    int c = tid & 63;
    int sub = tid >> 6;         // 0..3, 16 nodes each
    unsigned long long w2[8], t2[8];   // packed (w[2k], w[2k+1])
#pragma unroll
    for (int k = 0; k < 8; k++) {
        PACK_F32X2(w2[k], W2[(2 * k) * OUTC + c], W2[(2 * k + 1) * OUTC + c]);
        PACK_F32X2(t2[k], T2[(2 * k) * OUTC + c], T2[(2 * k + 1) * OUTC + c]);
    }
    float bb2 = b2[c];
    float tb2 = t2b[c];

#pragma unroll 1
    for (int n = 0; n < 16; n++) {
        int r = blockIdx.x * 64 + sub * 16 + n;
        if (r >= NN) break;
        unsigned long long acc1v, acc2v;
        PACK_F32X2(acc1v, bb2, 0.f);
        PACK_F32X2(acc2v, 0.f, 0.f);

        const ulonglong2* ar = (const ulonglong2*)(g_agg + (size_t)r * HID);
        const uint4* hr = (const uint4*)(g_hsh + (size_t)r * HID);
        uint4 u0 = __ldg(&hr[0]);   // halves 0..7 (broadcast across 64 lanes)
        uint4 u1 = __ldg(&hr[1]);   // halves 8..15
#pragma unroll
        for (int qq = 0; qq < 4; qq++) {
            ulonglong2 a = __ldg(&ar[qq]);   // agg floats 4qq..4qq+3
            FMA_F32X2(acc1v, a.x, w2[2 * qq],     acc1v);
            FMA_F32X2(acc1v, a.y, w2[2 * qq + 1], acc1v);
        }
        // hs dot T2 (convert to fp32 pairs, FFMA2)
        {
            float2 f0 = __half22float2(*(__half2*)&u0.x);
            float2 f1 = __half22float2(*(__half2*)&u0.y);
            float2 f2 = __half22float2(*(__half2*)&u0.z);
            float2 f3 = __half22float2(*(__half2*)&u0.w);
            float2 f4 = __half22float2(*(__half2*)&u1.x);
            float2 f5 = __half22float2(*(__half2*)&u1.y);
            float2 f6 = __half22float2(*(__half2*)&u1.z);
            float2 f7 = __half22float2(*(__half2*)&u1.w);
            unsigned long long hv;
            PACK_F32X2(hv, f0.x, f0.y); FMA_F32X2(acc2v, hv, t2[0], acc2v);
            PACK_F32X2(hv, f1.x, f1.y); FMA_F32X2(acc2v, hv, t2[1], acc2v);
            PACK_F32X2(hv, f2.x, f2.y); FMA_F32X2(acc2v, hv, t2[2], acc2v);
            PACK_F32X2(hv, f3.x, f3.y); FMA_F32X2(acc2v, hv, t2[3], acc2v);
            PACK_F32X2(hv, f4.x, f4.y); FMA_F32X2(acc2v, hv, t2[4], acc2v);
            PACK_F32X2(hv, f5.x, f5.y); FMA_F32X2(acc2v, hv, t2[5], acc2v);
            PACK_F32X2(hv, f6.x, f6.y); FMA_F32X2(acc2v, hv, t2[6], acc2v);
            PACK_F32X2(hv, f7.x, f7.y); FMA_F32X2(acc2v, hv, t2[7], acc2v);
        }
        float l1, h1, l2, h2;
        UNPACK_F32X2(l1, h1, acc1v);
        UNPACK_F32X2(l2, h2, acc2v);
        float rdn = __fdividef(1.0f, g_dinv[r]);   // sqrt(deg+1), folded post-dot
        out[(size_t)r * OUTC + c] = fmaxf(l1 + h1, 0.f) + (l2 + h2) * rdn + tb2;
    }
}

extern "C" void kernel_launch(void* const* d_in, const int* in_sizes, int n_in,
                              void* d_out, int out_size) {
    const float* x   = (const float*)d_in[0];
    const int*   ei  = (const int*)d_in[1];   // int32 (JAX demotes int64)
    const float* W1  = (const float*)d_in[2];
    const float* b1  = (const float*)d_in[3];
    const float* W2  = (const float*)d_in[4];
    const float* b2  = (const float*)d_in[5];
    const float* T1  = (const float*)d_in[6];
    const float* t1b = (const float*)d_in[7];
    const float* T2  = (const float*)d_in[8];
    const float* t2b = (const float*)d_in[9];
    float* out = (float*)d_out;

    // fork s2 from capture-origin stream; combined gemm1 (single x read)
    cudaEventRecord(g_evFork, 0);
    cudaStreamWaitEvent(g_s2, g_evFork, 0);
    k_gemm1<<<(NN + 255) / 256, 128, 0, g_s2>>>(x, W1, T1, t1b);
    cudaEventRecord(g_evS2, g_s2);

    // main: bucket CSR fill (t=0, overlaps gemm1)
    k_fill2<<<(NE / 4 + 255) / 256, 256>>>(ei);

    // dinv + scale + fp16 pack (needs fill and gemm1)
    cudaStreamWaitEvent(0, g_evS2, 0);
    k_dinv<<<(NN * 4 + 255) / 256, 256>>>();

    k_gather_h<<<(NN * 4 + 127) / 128, 128>>>(b1);
    k_gather2<<<(NN * 4 + 127) / 128, 128>>>();
    k_out<<<(NN + 63) / 64, 256>>>(W2, b2, T2, t2b, out);
}

// round 16
// speedup vs baseline: 1.1797x; 1.1797x over previous
#include <cuda_runtime.h>
#include <cuda_fp16.h>

#define NN 100000
#define NE 3200000
#define HID 16
#define OUTC 64
#define INC 128
#define CAP 128   // per-node capacity (deg ~ Poisson(32); 12-sigma safe, fixed input graph)

// packed fp32x2 FMA (sm_103a; ptxas never emits FFMA2 from C++)
#define FMA_F32X2(d, a, b, c) \
    asm("fma.rn.f32x2 %0, %1, %2, %3;" : "=l"(d) : "l"(a), "l"(b), "l"(c))
#define PACK_F32X2(out, lo, hi) \
    asm("mov.b64 %0, {%1, %2};" : "=l"(out) : "f"(lo), "f"(hi))
#define UNPACK_F32X2(lo, hi, in) \
    asm("mov.b64 {%0, %1}, %2;" : "=f"(lo), "=f"(hi) : "l"(in))

// ---- scratch (device globals; .bss zero-initialized at module load) ----
__device__ int    g_cnt[NN];               // invariant: zero at entry (re-zeroed in k_g2out)
__device__ float  g_dinv[NN];
__device__ int    g_rowidx[NN * CAP + 4];  // +4: prefetch over-read pad
__device__ float  g_xW1r[NN * HID];        // raw x@W1 (fp32)
__device__ __align__(16) __half g_xW1h[NN * HID];  // (x@W1)*dinv, fp16 rows (32 B)
__device__ float  g_id1[NN * HID];         // x@T1 + t1b (fp32)
__device__ __align__(16) __half g_hsh[NN * HID];   // (relu+id1)*dn, fp16 rows (32 B)

// ---- second stream + events (created pre-main; no device memory) ----
static cudaStream_t g_s2;
static cudaEvent_t  g_evFork, g_evS2;
namespace {
struct S2Init {
    S2Init() {
        cudaStreamCreateWithFlags(&g_s2, cudaStreamNonBlocking);
        cudaEventCreateWithFlags(&g_evFork, cudaEventDisableTiming);
        cudaEventCreateWithFlags(&g_evS2, cudaEventDisableTiming);
    }
};
static S2Init s2init;
}

// ---- single-pass bucket fill ----
__global__ void k_fill2(const int* __restrict__ ei) {
    int t = blockIdx.x * blockDim.x + threadIdx.x;
    if (t < NE / 4) {
        int4 r4 = ((const int4*)ei)[t];
        int4 c4 = ((const int4*)(ei + NE))[t];
        g_rowidx[c4.x * CAP + atomicAdd(&g_cnt[c4.x], 1)] = r4.x;
        g_rowidx[c4.y * CAP + atomicAdd(&g_cnt[c4.y], 1)] = r4.y;
        g_rowidx[c4.z * CAP + atomicAdd(&g_cnt[c4.z], 1)] = r4.z;
        g_rowidx[c4.w * CAP + atomicAdd(&g_cnt[c4.w], 1)] = r4.w;
    }
}

// ---- combined GEMM1 (s2): 2 rows/thread, FFMA2. xW1r = x@W1 ; id1 = x@T1+t1b ----
__global__ void __launch_bounds__(128) k_gemm1(const float* __restrict__ x,
                        const float* __restrict__ W1,
                        const float* __restrict__ T1,
                        const float* __restrict__ t1b) {
    __shared__ __align__(16) float ws[INC * 32];   // [k][j]: j<16 W1, j>=16 T1
    for (int i = threadIdx.x; i < INC * HID; i += blockDim.x) {
        int k = i / HID, j = i % HID;
        ws[k * 32 + j]      = W1[i];
        ws[k * 32 + 16 + j] = T1[i];
    }
    __syncthreads();

    int r0 = blockIdx.x * 256 + threadIdx.x;   // rows r0 and r0+128
    int r1 = r0 + 128;
    bool has0 = r0 < NN, has1 = r1 < NN;
    if (!has0) return;

    unsigned long long accA[16], accB[16];
#pragma unroll
    for (int j = 0; j < 16; j++) { accA[j] = 0ULL; accB[j] = 0ULL; }

    const float4* xrA = (const float4*)(x + (size_t)r0 * INC);
    const float4* xrB = (const float4*)(x + (size_t)r1 * INC);
#pragma unroll 4
    for (int kk = 0; kk < INC / 4; kk++) {
        float4 xa = xrA[kk];
        float4 xb = has1 ? xrB[kk] : make_float4(0.f, 0.f, 0.f, 0.f);
        float xsA[4] = {xa.x, xa.y, xa.z, xa.w};
        float xsB[4] = {xb.x, xb.y, xb.z, xb.w};
#pragma unroll
        for (int s = 0; s < 4; s++) {
            unsigned long long xdA, xdB;
            PACK_F32X2(xdA, xsA[s], xsA[s]);
            PACK_F32X2(xdB, xsB[s], xsB[s]);
            const ulonglong2* wrow = (const ulonglong2*)(ws + (kk * 4 + s) * 32);
#pragma unroll
            for (int q = 0; q < 8; q++) {
                ulonglong2 wl = wrow[q];     // LDS.128 broadcast: floats 4q..4q+3
                FMA_F32X2(accA[2 * q],     xdA, wl.x, accA[2 * q]);
                FMA_F32X2(accA[2 * q + 1], xdA, wl.y, accA[2 * q + 1]);
                FMA_F32X2(accB[2 * q],     xdB, wl.x, accB[2 * q]);
                FMA_F32X2(accB[2 * q + 1], xdB, wl.y, accB[2 * q + 1]);
            }
        }
    }

    float a[32], b[32];
#pragma unroll
    for (int j = 0; j < 16; j++) {
        UNPACK_F32X2(a[2 * j], a[2 * j + 1], accA[j]);
        UNPACK_F32X2(b[2 * j], b[2 * j + 1], accB[j]);
    }
    {
        float4* o1 = (float4*)(g_xW1r + r0 * HID);
        float4* o2 = (float4*)(g_id1 + r0 * HID);
#pragma unroll
        for (int q = 0; q < 4; q++) {
            o1[q] = make_float4(a[q * 4 + 0], a[q * 4 + 1], a[q * 4 + 2], a[q * 4 + 3]);
            o2[q] = make_float4(a[16 + q * 4 + 0] + t1b[q * 4 + 0],
                                a[16 + q * 4 + 1] + t1b[q * 4 + 1],
                                a[16 + q * 4 + 2] + t1b[q * 4 + 2],
                                a[16 + q * 4 + 3] + t1b[q * 4 + 3]);
        }
    }
    if (has1) {
        float4* o1 = (float4*)(g_xW1r + r1 * HID);
        float4* o2 = (float4*)(g_id1 + r1 * HID);
#pragma unroll
        for (int q = 0; q < 4; q++) {
            o1[q] = make_float4(b[q * 4 + 0], b[q * 4 + 1], b[q * 4 + 2], b[q * 4 + 3]);
            o2[q] = make_float4(b[16 + q * 4 + 0] + t1b[q * 4 + 0],
                                b[16 + q * 4 + 1] + t1b[q * 4 + 1],
                                b[16 + q * 4 + 2] + t1b[q * 4 + 2],
                                b[16 + q * 4 + 3] + t1b[q * 4 + 3]);
        }
    }
}

// ---- dinv + scale + fp16 pack: xW1h = half(xW1r * dinv) ----
__global__ void k_dinv() {
    int gid = blockIdx.x * blockDim.x + threadIdx.x;   // node*4+q
    int node = gid >> 2;
    if (node >= NN) return;
    float dn = rsqrtf((float)g_cnt[node] + 1.0f);
    if ((gid & 3) == 0) g_dinv[node] = dn;
    float4 v = ((const float4*)g_xW1r)[gid];
    __half2 h0 = __floats2half2_rn(v.x * dn, v.y * dn);
    __half2 h1 = __floats2half2_rn(v.z * dn, v.w * dn);
    uint2 u;
    u.x = *(unsigned int*)&h0;
    u.y = *(unsigned int*)&h1;
    ((uint2*)g_xW1h)[gid] = u;
}

// ---- gather core: fp16 rows (32 B); index prefetch; fp32 accumulation ----
__device__ __forceinline__ float4 gather_node_h(const __half* __restrict__ srcH,
                                                int node, int q, int deg) {
    const uint2* src2 = (const uint2*)srcH;
    const int4* idx4 = (const int4*)(g_rowidx + node * CAP);
    float4 acc = make_float4(0.f, 0.f, 0.f, 0.f);
    int nIter = deg >> 2;
    if (nIter > 0) {
        int4 r = __ldg(&idx4[0]);
        for (int it = 0; it < nIter; it++) {
            int4 rn = __ldg(&idx4[it + 1]);   // prefetch next (pad makes over-read safe)
            uint2 ua = __ldg(&src2[r.x * 4 + q]);
            uint2 ub = __ldg(&src2[r.y * 4 + q]);
            uint2 uc = __ldg(&src2[r.z * 4 + q]);
            uint2 ud = __ldg(&src2[r.w * 4 + q]);
            float2 a0 = __half22float2(*(__half2*)&ua.x), a1 = __half22float2(*(__half2*)&ua.y);
            float2 b0 = __half22float2(*(__half2*)&ub.x), b1 = __half22float2(*(__half2*)&ub.y);
            float2 c0 = __half22float2(*(__half2*)&uc.x), c1 = __half22float2(*(__half2*)&uc.y);
            float2 d0 = __half22float2(*(__half2*)&ud.x), d1 = __half22float2(*(__half2*)&ud.y);
            acc.x += (a0.x + b0.x) + (c0.x + d0.x);
            acc.y += (a0.y + b0.y) + (c0.y + d0.y);
            acc.z += (a1.x + b1.x) + (c1.x + d1.x);
            acc.w += (a1.y + b1.y) + (c1.y + d1.y);
            r = rn;
        }
    }
    for (int i = nIter << 2; i < deg; i++) {
        int r0 = g_rowidx[node * CAP + i];
        uint2 ua = __ldg(&src2[r0 * 4 + q]);
        float2 a0 = __half22float2(*(__half2*)&ua.x), a1 = __half22float2(*(__half2*)&ua.y);
        acc.x += a0.x; acc.y += a0.y; acc.z += a1.x; acc.w += a1.y;
    }
    uint2 us = __ldg(&src2[node * 4 + q]);   // self loop
    float2 s0 = __half22float2(*(__half2*)&us.x), s1 = __half22float2(*(__half2*)&us.y);
    acc.x += s0.x; acc.y += s0.y; acc.z += s1.x; acc.w += s1.y;
    return acc;
}

// ---- Gather pass 0: hs = half((relu(dn*acc + b1) + id1) * dn) ----
__global__ void k_gather_h(const float* __restrict__ b1) {
    int gid = blockIdx.x * blockDim.x + threadIdx.x;
    int node = gid >> 2;
    int q = gid & 3;
    if (node >= NN) return;

    int deg = g_cnt[node];
    float4 acc = gather_node_h(g_xW1h, node, q, deg);
    float dn = g_dinv[node];
    float4 bb = ((const float4*)b1)[q];
    float4 id = ((const float4*)g_id1)[gid];
    float hx = (fmaxf(dn * acc.x + bb.x, 0.f) + id.x) * dn;
    float hy = (fmaxf(dn * acc.y + bb.y, 0.f) + id.y) * dn;
    float hz = (fmaxf(dn * acc.z + bb.z, 0.f) + id.z) * dn;
    float hw = (fmaxf(dn * acc.w + bb.w, 0.f) + id.w) * dn;
    __half2 h0 = __floats2half2_rn(hx, hy);
    __half2 h1 = __floats2half2_rn(hz, hw);
    uint2 u;
    u.x = *(unsigned int*)&h0;
    u.y = *(unsigned int*)&h1;
    ((uint2*)g_hsh)[gid] = u;
}

// ---- Fused gather2 + output GEMM (FFMA2 GEMM phase). h = hs*sqrt(deg+1). ----
__global__ void k_g2out(const float* __restrict__ W2,
                        const float* __restrict__ b2,
                        const float* __restrict__ T2,
                        const float* __restrict__ t2b,
                        float* __restrict__ out) {
    __shared__ __align__(16) float s_agg[64 * HID];
    __shared__ __align__(16) float s_h[64 * HID];

    int tid = threadIdx.x;
    int nl = tid >> 2;          // node_local 0..63
    int q = tid & 3;
    int node = blockIdx.x * 64 + nl;

    if (node < NN) {
        int deg = g_cnt[node];
        float4 acc = gather_node_h(g_hsh, node, q, deg);
        float dn = g_dinv[node];
        ((float4*)s_agg)[nl * 4 + q] =
            make_float4(dn * acc.x, dn * acc.y, dn * acc.z, dn * acc.w);
        float rdn = sqrtf((float)deg + 1.0f);    // 1/dn
        uint2 us = ((const uint2*)g_hsh)[node * 4 + q];
        float2 s0 = __half22float2(*(__half2*)&us.x), s1 = __half22float2(*(__half2*)&us.y);
        ((float4*)s_h)[nl * 4 + q] =
            make_float4(s0.x * rdn, s0.y * rdn, s1.x * rdn, s1.y * rdn);
    }
    __syncthreads();

    // restore zero-invariant (all cnt reads for this tile are done)
    if (tid < 64) {
        int n2 = blockIdx.x * 64 + tid;
        if (n2 < NN) g_cnt[n2] = 0;
    }

    int c = tid & 63;
    int sub = tid >> 6;         // 0..3, 16 nodes each
    unsigned long long w2[8], t2[8];   // packed (w[2k], w[2k+1])
#pragma unroll
    for (int k = 0; k < 8; k++) {
        PACK_F32X2(w2[k], W2[(2 * k) * OUTC + c], W2[(2 * k + 1) * OUTC + c]);
        PACK_F32X2(t2[k], T2[(2 * k) * OUTC + c], T2[(2 * k + 1) * OUTC + c]);
    }
    float bb2 = b2[c];
    float tb2 = t2b[c];

#pragma unroll 1
    for (int n = 0; n < 16; n++) {
        int nl2 = sub * 16 + n;
        int r = blockIdx.x * 64 + nl2;
        if (r >= NN) break;
        unsigned long long acc1v, acc2v;
        PACK_F32X2(acc1v, bb2, 0.f);
        PACK_F32X2(acc2v, tb2, 0.f);
        const ulonglong2* ar = (const ulonglong2*)(s_agg + nl2 * HID);
        const ulonglong2* hr = (const ulonglong2*)(s_h + nl2 * HID);
#pragma unroll
        for (int qq = 0; qq < 4; qq++) {
            ulonglong2 a = ar[qq];   // floats 4qq..4qq+3 as two f32x2
            ulonglong2 h = hr[qq];
            FMA_F32X2(acc1v, a.x, w2[2 * qq],     acc1v);
            FMA_F32X2(acc1v, a.y, w2[2 * qq + 1], acc1v);
            FMA_F32X2(acc2v, h.x, t2[2 * qq],     acc2v);
            FMA_F32X2(acc2v, h.y, t2[2 * qq + 1], acc2v);
        }
        float l1, h1, l2, h2;
        UNPACK_F32X2(l1, h1, acc1v);
        UNPACK_F32X2(l2, h2, acc2v);
        out[(size_t)r * OUTC + c] = fmaxf(l1 + h1, 0.f) + (l2 + h2);
    }
}

extern "C" void kernel_launch(void* const* d_in, const int* in_sizes, int n_in,
                              void* d_out, int out_size) {
    const float* x   = (const float*)d_in[0];
    const int*   ei  = (const int*)d_in[1];   // int32 (JAX demotes int64)
    const float* W1  = (const float*)d_in[2];
    const float* b1  = (const float*)d_in[3];
    const float* W2  = (const float*)d_in[4];
    const float* b2  = (const float*)d_in[5];
    const float* T1  = (const float*)d_in[6];
    const float* t1b = (const float*)d_in[7];
    const float* T2  = (const float*)d_in[8];
    const float* t2b = (const float*)d_in[9];
    float* out = (float*)d_out;

    // fork s2 from capture-origin stream; combined gemm1 (single x read)
    cudaEventRecord(g_evFork, 0);
    cudaStreamWaitEvent(g_s2, g_evFork, 0);
    k_gemm1<<<(NN + 255) / 256, 128, 0, g_s2>>>(x, W1, T1, t1b);
    cudaEventRecord(g_evS2, g_s2);

    // main: bucket CSR fill (t=0, overlaps gemm1)
    k_fill2<<<(NE / 4 + 255) / 256, 256>>>(ei);

    // dinv + scale + fp16 pack (needs fill and gemm1)
    cudaStreamWaitEvent(0, g_evS2, 0);
    k_dinv<<<(NN * 4 + 255) / 256, 256>>>();

    k_gather_h<<<(NN * 4 + 127) / 128, 128>>>(b1);
    k_g2out<<<(NN + 63) / 64, 256>>>(W2, b2, T2, t2b, out);
}